// round 6
// baseline (speedup 1.0000x reference)
#include <cuda_runtime.h>
#include <cuda_fp16.h>

#define NN 100000
#define EE 1600000
#define GG 2048
#define DD 128
#define BN_EPS 1e-5f

// bit-cast helpers (register renames only)
__device__ __forceinline__ unsigned int h2_as_u(__half2 h) {
    union { __half2 h; unsigned int u; } c; c.h = h; return c.u;
}
__device__ __forceinline__ __half2 u_as_h2(unsigned int u) {
    union { unsigned int u; __half2 h; } c; c.u = u; return c.h;
}

// ---------------- scratch (static device globals; no allocs allowed) ----------------
__device__ uint4  g_linS[NN * 8];    // fp16 dinv-scaled GEMM output: NN x 128 halves
__device__ __half g_hh[NN * DD];     // post-activation features (fp16, GEMM A input)
__device__ int    g_row[EE];
__device__ int    g_col[EE];
__device__ int    g_batch[NN];
__device__ int    g_deg[NN];
__device__ float  g_dinv[NN];
__device__ int    g_off[NN + 1];
__device__ int    g_cursor[NN];
__device__ int    g_csr[EE];
__device__ int    g_bsum[256];
__device__ float  g_stats4[3][2 * DD];  // per-layer BN stats (sum, sumsq)
__device__ __half g_Wph[DD * DD];    // scale-folded weights, n-major, fp16 hi
__device__ __half g_Wpl[DD * DD];    // fp16 lo residual
__device__ float  g_rvec[DD];        // shift @ W
__device__ float  g_pool[GG * DD];
__device__ float  g_cnt[GG];
__device__ int    g_is32;

__device__ __forceinline__ float lrelu(float x) { return x > 0.f ? x : 0.01f * x; }

// ---------------- setup: zero buffers + detect index width ----------------
__global__ void k_init(const void* ei) {
    int i = blockIdx.x * blockDim.x + threadIdx.x;
    if (i < NN) g_deg[i] = 0;
    if (i < GG * DD) g_pool[i] = 0.f;
    if (i < GG) g_cnt[i] = 0.f;
    if (i < 3 * 2 * DD) ((float*)g_stats4)[i] = 0.f;
    if (blockIdx.x == 0) {
        __shared__ int bad;
        if (threadIdx.x == 0) bad = 0;
        __syncthreads();
        const long long* p = (const long long*)ei;
        for (int j = threadIdx.x; j < 4096; j += blockDim.x) {
            long long v = p[j];
            if (v < 0 || v >= NN) bad = 1;
        }
        __syncthreads();
        if (threadIdx.x == 0) g_is32 = bad;
    }
}

// convert indices + degree histogram + batch convert + graph-size histogram
__global__ void k_convert_all(const void* ei, const void* bidx) {
    int e = blockIdx.x * blockDim.x + threadIdx.x;
    int is32 = g_is32;
    if (e < EE) {
        int r, c;
        if (is32) {
            const int* p = (const int*)ei;
            r = p[e]; c = p[EE + e];
        } else {
            const long long* p = (const long long*)ei;
            r = (int)p[e]; c = (int)p[EE + e];
        }
        g_row[e] = r;
        g_col[e] = c;
        atomicAdd(&g_deg[c], 1);
    }
    if (e < NN) {
        int b = is32 ? ((const int*)bidx)[e] : (int)((const long long*)bidx)[e];
        g_batch[e] = b;
        atomicAdd(&g_cnt[b], 1.0f);
    }
}

// ---------------- scan of deg -> off ----------------
__global__ void k_scanA() {
    __shared__ int s[256];
    int b = blockIdx.x, t = threadIdx.x;
    int base = b * 512 + t * 2;
    int v0 = (base < NN) ? g_deg[base] : 0;
    int v1 = (base + 1 < NN) ? g_deg[base + 1] : 0;
    int tsum = v0 + v1;
    s[t] = tsum;
    __syncthreads();
    int val = tsum;
    for (int d = 1; d < 256; d <<= 1) {
        int o = (t >= d) ? s[t - d] : 0;
        __syncthreads();
        val += o;
        s[t] = val;
        __syncthreads();
    }
    int excl = val - tsum;
    if (base < NN) g_off[base] = excl;
    if (base + 1 < NN) g_off[base + 1] = excl + v0;
    if (t == 255) g_bsum[b] = val;
}

// finalize: redundant 256-scan of block sums per block + dinv (scanB folded in)
__global__ void k_scanC() {
    __shared__ int s[256], ex[256];
    int t = threadIdx.x;
    int v = g_bsum[t];
    s[t] = v;
    __syncthreads();
    int val = v;
    for (int d = 1; d < 256; d <<= 1) {
        int o = (t >= d) ? s[t - d] : 0;
        __syncthreads();
        val += o;
        s[t] = val;
        __syncthreads();
    }
    ex[t] = val - v;
    __syncthreads();
    int i = blockIdx.x * blockDim.x + t;
    if (i < NN) {
        int o = g_off[i] + ex[i >> 9];
        g_off[i] = o;
        g_cursor[i] = o;
        g_dinv[i] = rsqrtf((float)g_deg[i] + 1.0f);
    }
    if (i == 0) g_off[NN] = EE;
}

__global__ void k_scatter() {
    int e = blockIdx.x * blockDim.x + threadIdx.x;
    if (e < EE) {
        int c = g_col[e];
        int slot = atomicAdd(&g_cursor[c], 1);
        g_csr[slot] = g_row[e];
    }
}

// ---------------- layer 0 GEMM: linS = fp16( dinv * (x[N,9] @ W0[9,128]) ) ----------------
__global__ void __launch_bounds__(256) k_gemm0(const float* __restrict__ x,
                                               const float* __restrict__ W0) {
    __shared__ float Ws[9 * DD];
    for (int i = threadIdx.x; i < 9 * DD; i += blockDim.x) Ws[i] = W0[i];
    __syncthreads();
    int gid = blockIdx.x * blockDim.x + threadIdx.x;
    if (gid >= NN * DD) return;
    int i = gid >> 7, f = gid & 127;
    float s = 0.f;
#pragma unroll
    for (int k = 0; k < 9; k++) s += x[i * 9 + k] * Ws[k * DD + f];
    ((__half*)g_linS)[gid] = __float2half_rn(g_dinv[i] * s);
}

// ---------------- weight prep (BN folded, computed in-kernel from stats) ----------------
// blocks 0..63: Wph/Wpl (n-major, hi/lo split). block 64: rvec = shift @ W.
__global__ void __launch_bounds__(256) k_wprep(const float* __restrict__ W,
                                               const float* __restrict__ gam,
                                               const float* __restrict__ bet,
                                               int slot) {
    const float* st = g_stats4[slot];
    if (blockIdx.x < 64) {
        int idx = blockIdx.x * 256 + threadIdx.x;     // = k*128+n
        int k = idx >> 7, n = idx & 127;
        float m = st[k] * (1.0f / NN);
        float v = st[DD + k] * (1.0f / NN) - m * m;
        float sc = gam[k] * rsqrtf(fmaxf(v, 0.f) + BN_EPS);
        float w = sc * W[idx];
        __half hi = __float2half_rn(w);
        g_Wph[n * DD + k] = hi;
        g_Wpl[n * DD + k] = __float2half_rn(w - __half2float(hi));
    } else {
        __shared__ float sh[DD];
        int t = threadIdx.x;
        if (t < DD) {
            float m = st[t] * (1.0f / NN);
            float v = st[DD + t] * (1.0f / NN) - m * m;
            float sc = gam[t] * rsqrtf(fmaxf(v, 0.f) + BN_EPS);
            sh[t] = bet[t] - m * sc;
        }
        __syncthreads();
        if (t < DD) {
            float s = 0.f;
#pragma unroll 8
            for (int k = 0; k < DD; k++) s += sh[k] * W[k * DD + t];
            g_rvec[t] = s;
        }
    }
}

// ---------------- main GEMM (HMMA, W hi/lo split): linS = fp16( dinv*(h@W' + rvec) ) ----------------
// dynamic smem: BsH [128][136] halves, then BsL [128][136]
#define BPITCH 136
#define BS_LO (DD * BPITCH)
__global__ void __launch_bounds__(256) k_gemm128() {
    extern __shared__ __half Bs[];
    int tid = threadIdx.x;
    for (int idx = tid * 8; idx < DD * DD; idx += 256 * 8) {
        int n = idx >> 7, k = idx & 127;
        *(uint4*)&Bs[n * BPITCH + k] = *(const uint4*)&g_Wph[idx];
        *(uint4*)&Bs[BS_LO + n * BPITCH + k] = *(const uint4*)&g_Wpl[idx];
    }
    __syncthreads();

    int wid = tid >> 5, lane = tid & 31;
    int qr = lane >> 2, qp = lane & 3;
    int rowbase = blockIdx.x * 128 + wid * 16;
    int r0 = rowbase + qr, r1 = rowbase + qr + 8;
    bool ok0 = r0 < NN, ok1 = r1 < NN;
    const unsigned* A0 = (const unsigned*)(g_hh + (size_t)r0 * DD);
    const unsigned* A1 = (const unsigned*)(g_hh + (size_t)r1 * DD);

    float acc[16][4];
#pragma unroll
    for (int nt = 0; nt < 16; nt++)
#pragma unroll
        for (int j = 0; j < 4; j++) acc[nt][j] = 0.f;

#pragma unroll
    for (int kt = 0; kt < 8; kt++) {
        int k0 = kt * 16;
        unsigned a0 = 0, a1 = 0, a2 = 0, a3 = 0;
        if (ok0) { a0 = A0[k0 / 2 + qp]; a2 = A0[k0 / 2 + 4 + qp]; }
        if (ok1) { a1 = A1[k0 / 2 + qp]; a3 = A1[k0 / 2 + 4 + qp]; }
#pragma unroll
        for (int nt = 0; nt < 16; nt++) {
            int n = nt * 8 + qr;
            unsigned bh0 = *(const unsigned*)&Bs[n * BPITCH + k0 + qp * 2];
            unsigned bh1 = *(const unsigned*)&Bs[n * BPITCH + k0 + 8 + qp * 2];
            asm volatile(
                "mma.sync.aligned.m16n8k16.row.col.f32.f16.f16.f32 "
                "{%0,%1,%2,%3}, {%4,%5,%6,%7}, {%8,%9}, {%0,%1,%2,%3};"
                : "+f"(acc[nt][0]), "+f"(acc[nt][1]), "+f"(acc[nt][2]), "+f"(acc[nt][3])
                : "r"(a0), "r"(a1), "r"(a2), "r"(a3), "r"(bh0), "r"(bh1));
            unsigned bl0 = *(const unsigned*)&Bs[BS_LO + n * BPITCH + k0 + qp * 2];
            unsigned bl1 = *(const unsigned*)&Bs[BS_LO + n * BPITCH + k0 + 8 + qp * 2];
            asm volatile(
                "mma.sync.aligned.m16n8k16.row.col.f32.f16.f16.f32 "
                "{%0,%1,%2,%3}, {%4,%5,%6,%7}, {%8,%9}, {%0,%1,%2,%3};"
                : "+f"(acc[nt][0]), "+f"(acc[nt][1]), "+f"(acc[nt][2]), "+f"(acc[nt][3])
                : "r"(a0), "r"(a1), "r"(a2), "r"(a3), "r"(bl0), "r"(bl1));
        }
    }

    // epilogue: linS = fp16( dinv * (acc + rvec) )
    float d0 = ok0 ? g_dinv[r0] : 0.f;
    float d1 = ok1 ? g_dinv[r1] : 0.f;
    unsigned* o0 = (unsigned*)((__half*)g_linS + (size_t)r0 * DD);
    unsigned* o1 = (unsigned*)((__half*)g_linS + (size_t)r1 * DD);
#pragma unroll
    for (int nt = 0; nt < 16; nt++) {
        int n = nt * 8 + qp * 2;
        float rv0 = g_rvec[n], rv1 = g_rvec[n + 1];
        if (ok0) {
            __half2 p = __floats2half2_rn(d0 * (acc[nt][0] + rv0), d0 * (acc[nt][1] + rv1));
            o0[n / 2] = h2_as_u(p);
        }
        if (ok1) {
            __half2 p = __floats2half2_rn(d1 * (acc[nt][2] + rv0), d1 * (acc[nt][3] + rv1));
            o1[n / 2] = h2_as_u(p);
        }
    }
}

// ---------------- SpMM: warp per destination node, fp16 gathers, 8-wide unroll ----------------
#define GATHER1(r)                                                      \
    {                                                                   \
        uint2 v = lin2[(r) * 32 + lane];                                \
        float2 f;                                                       \
        f = __half22float2(u_as_h2(v.x)); ax += f.x; ay += f.y;         \
        f = __half22float2(u_as_h2(v.y)); az += f.x; aw += f.y;         \
    }

template <bool FINAL>
__global__ void __launch_bounds__(256) k_spmm(const float* __restrict__ bias,
                                              float* __restrict__ stats) {
    __shared__ float ssum[DD], ssq[DD];
    int tid = threadIdx.x;
    if (!FINAL) {
        for (int i = tid; i < DD; i += blockDim.x) { ssum[i] = 0.f; ssq[i] = 0.f; }
        __syncthreads();
    }
    int lane = tid & 31;
    int gw = (blockIdx.x * blockDim.x + tid) >> 5;
    int nw = (gridDim.x * blockDim.x) >> 5;
    const uint2* lin2 = (const uint2*)g_linS;
    float4 b4 = ((const float4*)bias)[lane];
    float s0 = 0, s1 = 0, s2 = 0, s3 = 0, q0 = 0, q1 = 0, q2 = 0, q3 = 0;

    for (int i = gw; i < NN; i += nw) {
        int e0 = g_off[i], e1 = g_off[i + 1];
        float ax = 0.f, ay = 0.f, az = 0.f, aw = 0.f;
        int e = e0;
        for (; e + 8 <= e1; e += 8) {
            int r0 = g_csr[e],     r1 = g_csr[e + 1], r2 = g_csr[e + 2], r3 = g_csr[e + 3];
            int r4 = g_csr[e + 4], r5 = g_csr[e + 5], r6 = g_csr[e + 6], r7 = g_csr[e + 7];
            GATHER1(r0) GATHER1(r1) GATHER1(r2) GATHER1(r3)
            GATHER1(r4) GATHER1(r5) GATHER1(r6) GATHER1(r7)
        }
        for (; e + 4 <= e1; e += 4) {
            int r0 = g_csr[e], r1 = g_csr[e + 1], r2 = g_csr[e + 2], r3 = g_csr[e + 3];
            GATHER1(r0) GATHER1(r1) GATHER1(r2) GATHER1(r3)
        }
        for (; e < e1; e++) { int r = g_csr[e]; GATHER1(r) }
        GATHER1(i)   // self-loop
        float di = g_dinv[i];
        float hx = lrelu(fmaf(di, ax, b4.x));
        float hy = lrelu(fmaf(di, ay, b4.y));
        float hz = lrelu(fmaf(di, az, b4.z));
        float hw = lrelu(fmaf(di, aw, b4.w));
        if (!FINAL) {
            uint2 st;
            st.x = h2_as_u(__floats2half2_rn(hx, hy));
            st.y = h2_as_u(__floats2half2_rn(hz, hw));
            ((uint2*)g_hh)[i * 32 + lane] = st;
            s0 += hx; s1 += hy; s2 += hz; s3 += hw;
            q0 += hx * hx; q1 += hy * hy; q2 += hz * hz; q3 += hw * hw;
        } else {
            int bi = g_batch[i];
            float* p = &g_pool[bi * DD + lane * 4];
            atomicAdd(p + 0, hx);
            atomicAdd(p + 1, hy);
            atomicAdd(p + 2, hz);
            atomicAdd(p + 3, hw);
        }
    }

    if (!FINAL) {
        atomicAdd(&ssum[lane * 4 + 0], s0);
        atomicAdd(&ssum[lane * 4 + 1], s1);
        atomicAdd(&ssum[lane * 4 + 2], s2);
        atomicAdd(&ssum[lane * 4 + 3], s3);
        atomicAdd(&ssq[lane * 4 + 0], q0);
        atomicAdd(&ssq[lane * 4 + 1], q1);
        atomicAdd(&ssq[lane * 4 + 2], q2);
        atomicAdd(&ssq[lane * 4 + 3], q3);
        __syncthreads();
        for (int i = tid; i < DD; i += blockDim.x) {
            atomicAdd(&stats[i], ssum[i]);
            atomicAdd(&stats[DD + i], ssq[i]);
        }
    }
}

// ---------------- output head: warp per graph ----------------
__global__ void k_out(const float* __restrict__ Wout, const float* __restrict__ bout,
                      float* __restrict__ out) {
    int t = blockIdx.x * blockDim.x + threadIdx.x;
    int w = t >> 5, lane = t & 31;
    if (w >= GG) return;
    float4 p = ((const float4*)g_pool)[w * 32 + lane];
    float4 wv = ((const float4*)Wout)[lane];
    float d = p.x * wv.x + p.y * wv.y + p.z * wv.z + p.w * wv.w;
#pragma unroll
    for (int o = 16; o; o >>= 1) d += __shfl_down_sync(0xffffffffu, d, o);
    if (lane == 0) {
        float c = fmaxf(g_cnt[w], 1.0f);
        out[w] = d / c + bout[0];
    }
}

// ---------------- launch ----------------
extern "C" void kernel_launch(void* const* d_in, const int* in_sizes, int n_in,
                              void* d_out, int out_size) {
    const float* x     = (const float*)d_in[0];
    const void*  ei    = d_in[1];
    const void*  bidx  = d_in[2];
    const float* W0    = (const float*)d_in[3];
    const float* b0    = (const float*)d_in[4];
    const float* W1    = (const float*)d_in[5];
    const float* b1    = (const float*)d_in[6];
    const float* W2    = (const float*)d_in[7];
    const float* b2    = (const float*)d_in[8];
    const float* W3    = (const float*)d_in[9];
    const float* b3    = (const float*)d_in[10];
    const float* g1    = (const float*)d_in[11];
    const float* be1   = (const float*)d_in[12];
    const float* g2    = (const float*)d_in[13];
    const float* be2   = (const float*)d_in[14];
    const float* g3    = (const float*)d_in[15];
    const float* be3   = (const float*)d_in[16];
    const float* Wout  = (const float*)d_in[17];
    const float* bout  = (const float*)d_in[18];
    float* out = (float*)d_out;

    const int EB = (EE + 255) / 256;     // 6250
    const int NB = (NN + 255) / 256;     // 391
    const int GB = (NN + 127) / 128;     // 782
    const int SPMM_BLOCKS = 1184;        // 148 SMs x 8 blocks
    const int GEMM_SMEM = 2 * DD * BPITCH * (int)sizeof(__half);  // 69632

    static float* stats0 = nullptr;
    static float* stats1 = nullptr;
    static float* stats2 = nullptr;
    if (!stats0) {
        float* base;
        cudaGetSymbolAddress((void**)&base, g_stats4);
        stats0 = base;
        stats1 = base + 2 * DD;
        stats2 = base + 4 * DD;
        cudaFuncSetAttribute(k_gemm128, cudaFuncAttributeMaxDynamicSharedMemorySize, GEMM_SMEM);
    }

    // preprocessing
    k_init<<<(GG * DD + 255) / 256, 256>>>(ei);
    k_convert_all<<<EB, 256>>>(ei, bidx);
    k_scanA<<<256, 256>>>();
    k_scanC<<<NB, 256>>>();
    k_scatter<<<EB, 256>>>();

    // layer 0 (K=9)
    k_gemm0<<<(NN * DD) / 256, 256>>>(x, W0);
    k_spmm<false><<<SPMM_BLOCKS, 256>>>(b0, stats0);

    // layer 1
    k_wprep<<<65, 256>>>(W1, g1, be1, 0);
    k_gemm128<<<GB, 256, GEMM_SMEM>>>();
    k_spmm<false><<<SPMM_BLOCKS, 256>>>(b1, stats1);

    // layer 2
    k_wprep<<<65, 256>>>(W2, g2, be2, 1);
    k_gemm128<<<GB, 256, GEMM_SMEM>>>();
    k_spmm<false><<<SPMM_BLOCKS, 256>>>(b2, stats2);

    // layer 3 (final, fused pooling)
    k_wprep<<<65, 256>>>(W3, g3, be3, 2);
    k_gemm128<<<GB, 256, GEMM_SMEM>>>();
    k_spmm<true><<<SPMM_BLOCKS, 256>>>(b3, nullptr);

    // head
    k_out<<<(GG * 32 + 255) / 256, 256>>>(Wout, bout, out);

    (void)in_sizes; (void)n_in; (void)out_size;
}